// round 1
// baseline (speedup 1.0000x reference)
#include <cuda_runtime.h>
#include <cstdint>

#define NIMG   8
#define NANCH  25200
#define NCH    85
#define NC     80
#define CONF   0.96f
#define IOUT   0.45f
#define CAP    4096
#define MAXC   2048
#define DETS   300
#define CLSCAP 96

typedef unsigned long long u64;
typedef unsigned int u32;

// Device scratch (no allocations allowed)
__device__ int   g_count[NIMG];
__device__ float g_cscore[NIMG][CAP];
__device__ int   g_cidx[NIMG][CAP];

__global__ void k_zero() {
    if (threadIdx.x < NIMG) g_count[threadIdx.x] = 0;
}

// Filter: only anchors with obj > CONF can produce candidates (cls < 1).
__global__ void k_filter(const float* __restrict__ pred) {
    int anchor = blockIdx.x * blockDim.x + threadIdx.x;
    int img = blockIdx.y;
    if (anchor >= NANCH) return;
    const float* p = pred + ((size_t)img * NANCH + anchor) * NCH;
    float obj = __ldg(p + 4);
    if (obj > CONF) {
        #pragma unroll 4
        for (int c = 0; c < NC; c++) {
            float s = __ldg(p + 5 + c) * obj;
            if (s > CONF) {
                int pos = atomicAdd(&g_count[img], 1);
                if (pos < CAP) {
                    g_cscore[img][pos] = s;
                    g_cidx[img][pos]   = anchor * NC + c;
                }
            }
        }
    }
}

// Sort + per-class NMS + output. One block per image, 1024 threads.
// Dynamic smem layout:
//   [0,      32768)  u64 keys[4096]      (later reused as int clsList[80*96])
//   [32768,  65536)  float4 sbox[2048]   (raw xyxy boxes)
//   [65536,  73728)  float sscore[2048]
//   [73728,  81920)  int   slab[2048]
//   [81920,  90112)  int   keep[2048]
#define SMEM_BYTES 90112

__global__ __launch_bounds__(1024) void k_sortnms(const float* __restrict__ pred,
                                                  float* __restrict__ out) {
    extern __shared__ char smem[];
    u64*    keys    = (u64*)smem;
    float4* sbox    = (float4*)(smem + 32768);
    float*  sscore  = (float*)(smem + 65536);
    int*    slab    = (int*)(smem + 73728);
    int*    keep    = (int*)(smem + 81920);
    int*    clsList = (int*)smem;   // aliases keys AFTER extraction barrier

    __shared__ int wsum[32];
    __shared__ int totK;

    int img  = blockIdx.x;
    int tid  = threadIdx.x;
    int lane = tid & 31;
    int warp = tid >> 5;

    int n = g_count[img];
    if (n > CAP) n = CAP;

    // Load packed keys: descending (score, then ascending flat idx) matches
    // jax.lax.top_k ordering exactly. Scores > 0.96 => positive float bits
    // are monotone as u32.
    for (int t = tid; t < CAP; t += 1024) {
        u64 k = 0ull;
        if (t < n) {
            u32 sb = __float_as_uint(g_cscore[img][t]);
            u32 ib = ~(u32)g_cidx[img][t];
            k = ((u64)sb << 32) | ib;
        }
        keys[t] = k;
    }
    __syncthreads();

    // Bitonic sort, descending. Only sort 2048 if n fits (common case).
    int SN = (n <= MAXC) ? MAXC : CAP;
    for (int k = 2; k <= SN; k <<= 1) {
        for (int j = k >> 1; j > 0; j >>= 1) {
            for (int i = tid; i < SN; i += 1024) {
                int ixj = i ^ j;
                if (ixj > i) {
                    u64 a = keys[i], b = keys[ixj];
                    bool desc = ((i & k) == 0);
                    if (desc ? (a < b) : (a > b)) { keys[i] = b; keys[ixj] = a; }
                }
            }
            __syncthreads();
        }
    }

    int m = (n < MAXC) ? n : MAXC;

    // Extract candidates: gather boxes (raw xyxy — offset cancels per class).
    for (int t = tid; t < MAXC; t += 1024) {
        if (t < m) {
            u64 k = keys[t];
            float sc = __uint_as_float((u32)(k >> 32));
            int idx = (int)(~(u32)k);
            int anchor = idx / NC;
            int lbl = idx - anchor * NC;
            const float* p = pred + ((size_t)img * NANCH + anchor) * NCH;
            float cx = __ldg(p + 0), cy = __ldg(p + 1);
            float w  = __ldg(p + 2), h  = __ldg(p + 3);
            float4 b;
            b.x = cx - 0.5f * w; b.y = cy - 0.5f * h;
            b.z = cx + 0.5f * w; b.w = cy + 0.5f * h;
            sbox[t] = b; sscore[t] = sc; slab[t] = lbl; keep[t] = 1;
        } else {
            slab[t] = -1; keep[t] = 0;
        }
    }
    __syncthreads();  // keys dead; clsList may now alias it

    // Per-class greedy NMS. The +label*4 offset in the reference means
    // cross-class IoU == 0 (box extent <= 1.5 << 4), so NMS decomposes
    // exactly per class. Warp w handles classes w, w+32, w+64.
    for (int c = warp; c < NC; c += 32) {
        int* lst = clsList + c * CLSCAP;
        int cnt = 0;
        for (int base = 0; base < m; base += 32) {
            int t = base + lane;
            int lbl = (t < m) ? slab[t] : -1;
            u32 bm = __ballot_sync(0xffffffffu, lbl == c);
            if (lbl == c) {
                int pos = cnt + __popc(bm & ((1u << lane) - 1u));
                if (pos < CLSCAP) lst[pos] = t;
            }
            cnt += __popc(bm);
        }
        if (cnt > CLSCAP) cnt = CLSCAP;

        for (int a = 0; a < cnt - 1; a++) {
            __syncwarp();
            int pa = lst[a];
            if (keep[pa]) {
                float4 A = sbox[pa];
                float areaA = (A.z - A.x) * (A.w - A.y);
                for (int b = a + 1 + lane; b < cnt; b += 32) {
                    int pb = lst[b];
                    float4 B = sbox[pb];
                    float ltx = fmaxf(A.x, B.x), lty = fmaxf(A.y, B.y);
                    float rbx = fminf(A.z, B.z), rby = fminf(A.w, B.w);
                    float iw = fmaxf(rbx - ltx, 0.0f);
                    float ih = fmaxf(rby - lty, 0.0f);
                    float inter = iw * ih;
                    float areaB = (B.z - B.x) * (B.w - B.y);
                    float iou = inter / (areaA + areaB - inter + 1e-9f);
                    if (iou > IOUT) keep[pb] = 0;
                }
            }
        }
    }
    __syncthreads();

    // Block-wide exclusive scan of keep[] to get detection ranks
    // (kept candidates retain descending-score order == reference top-300).
    int t0 = 2 * tid, t1 = 2 * tid + 1;
    int k0 = keep[t0], k1 = keep[t1];
    int s = k0 + k1;
    int inc = s;
    #pragma unroll
    for (int o = 1; o < 32; o <<= 1) {
        int v = __shfl_up_sync(0xffffffffu, inc, o);
        if (lane >= o) inc += v;
    }
    if (lane == 31) wsum[warp] = inc;
    __syncthreads();
    if (warp == 0) {
        int v = wsum[lane];
        int iv = v;
        #pragma unroll
        for (int o = 1; o < 32; o <<= 1) {
            int u = __shfl_up_sync(0xffffffffu, iv, o);
            if (lane >= o) iv += u;
        }
        wsum[lane] = iv - v;          // exclusive warp offsets
        if (lane == 31) totK = iv;    // total kept
    }
    __syncthreads();

    int base = wsum[warp] + (inc - s);
    int r0 = base;
    int r1 = base + k0;
    if (k0 && r0 < DETS) {
        float* o = out + ((size_t)img * DETS + r0) * 6;
        float4 b = sbox[t0];
        o[0] = b.x; o[1] = b.y; o[2] = b.z; o[3] = b.w;
        o[4] = sscore[t0]; o[5] = (float)slab[t0];
    }
    if (k1 && r1 < DETS) {
        float* o = out + ((size_t)img * DETS + r1) * 6;
        float4 b = sbox[t1];
        o[0] = b.x; o[1] = b.y; o[2] = b.z; o[3] = b.w;
        o[4] = sscore[t1]; o[5] = (float)slab[t1];
    }

    int K = totK < DETS ? totK : DETS;
    for (int r = K + tid; r < DETS; r += 1024) {
        float* o = out + ((size_t)img * DETS + r) * 6;
        o[0] = 0.0f; o[1] = 0.0f; o[2] = 0.0f;
        o[3] = 0.0f; o[4] = 0.0f; o[5] = 0.0f;
    }
}

extern "C" void kernel_launch(void* const* d_in, const int* in_sizes, int n_in,
                              void* d_out, int out_size) {
    const float* pred = (const float*)d_in[0];
    float* out = (float*)d_out;

    cudaFuncSetAttribute(k_sortnms, cudaFuncAttributeMaxDynamicSharedMemorySize,
                         SMEM_BYTES);

    k_zero<<<1, 32>>>();
    dim3 g1((NANCH + 255) / 256, NIMG);
    k_filter<<<g1, 256>>>(pred);
    k_sortnms<<<NIMG, 1024, SMEM_BYTES>>>(pred, out);
}

// round 2
// speedup vs baseline: 2.3784x; 2.3784x over previous
#include <cuda_runtime.h>
#include <cstdint>

typedef unsigned long long u64;
typedef unsigned int u32;

#define NIMG   8
#define NANCH  25200
#define NCH    85
#define NC     80
#define CONF   0.96f
#define IOUT   0.45f
#define CLSCAP 64
#define KEPTCAP 4096
#define DETS   300
#define NBIN   4096
#define SB0    0x3F75C290u   // smallest float bits with s > 0.96f
#define FULL   0xFFFFFFFFu

// Device scratch (statics are zero-initialized; kernels reset counters after use
// so every graph replay starts clean).
__device__ int g_ccount[NIMG * NC];
__device__ u64 g_clist[NIMG * NC * CLSCAP];
__device__ int g_kcount[NIMG];
__device__ u64 g_kept[NIMG * KEPTCAP];

// ---------------------------------------------------------------------------
// K1: obj-gated filter, scatter candidates into per-(image,class) lists.
// Candidate iff cls*obj > CONF (implies obj > CONF since cls < 1).
// Key = (score_bits << 32) | ~flat_idx  -> desc sort == jax top_k order.
// ---------------------------------------------------------------------------
__global__ void k_filter(const float* __restrict__ pred) {
    int img    = blockIdx.y;
    int anchor = blockIdx.x * blockDim.x + threadIdx.x;
    int lane   = threadIdx.x & 31;

    float obj = 0.f;
    if (anchor < NANCH)
        obj = __ldg(pred + ((size_t)img * NANCH + anchor) * NCH + 4);

    u32 m = __ballot_sync(FULL, obj > CONF);
    while (m) {
        int src = __ffs(m) - 1;
        m &= m - 1;
        int   a = __shfl_sync(FULL, anchor, src);
        float o = __shfl_sync(FULL, obj, src);
        const float* row = pred + ((size_t)img * NANCH + a) * NCH + 5;
        #pragma unroll
        for (int r = 0; r < 3; r++) {
            int c = lane + r * 32;
            float s = (c < NC) ? __ldg(row + c) * o : 0.f;
            if (s > CONF) {
                int pos = atomicAdd(&g_ccount[img * NC + c], 1);
                if (pos < CLSCAP) {
                    u32 idx = (u32)(a * NC + c);
                    g_clist[(img * NC + c) * CLSCAP + pos] =
                        ((u64)__float_as_uint(s) << 32) | (u32)(~idx);
                }
            }
        }
    }
}

// Warp-register bitonic compare-exchange step (element e = lane or lane+32,
// partner e^j with j <= 16 so (e & j) == (lane & j)).
__device__ __forceinline__ u64 ce(u64 v, int j, bool desc, int lane) {
    u64 q = __shfl_xor_sync(FULL, v, j);
    bool keepmax = (((lane & j) == 0) == desc);
    bool vbig = v > q;
    return (keepmax == vbig) ? v : q;
}

// ---------------------------------------------------------------------------
// K2: one warp per (image, class): sort <=64 keys desc in registers, greedy
// NMS within the warp, append kept keys to per-image list.
// Cross-class IoU is exactly 0 in the reference (label*4 offset), so per-class
// greedy NMS is exact.
// ---------------------------------------------------------------------------
__global__ __launch_bounds__(256) void k_nms(const float* __restrict__ pred) {
    int img  = blockIdx.x;
    int warp = threadIdx.x >> 5;
    int lane = threadIdx.x & 31;
    int c    = blockIdx.y * 8 + warp;

    int cnt = g_ccount[img * NC + c];
    if (cnt > CLSCAP) cnt = CLSCAP;

    if (cnt > 0) {
        const u64* lst = &g_clist[(img * NC + c) * CLSCAP];
        u64 k0 = (lane < cnt)      ? lst[lane]      : 0ull;
        u64 k1 = (lane + 32 < cnt) ? lst[lane + 32] : 0ull;

        // Bitonic sort 64 descending. e0=lane, e1=lane+32.
        #pragma unroll
        for (int k = 2; k <= 16; k <<= 1) {
            #pragma unroll
            for (int j = k >> 1; j > 0; j >>= 1) {
                bool d = ((lane & k) == 0);
                k0 = ce(k0, j, d, lane);
                k1 = ce(k1, j, d, lane);
            }
        }
        // k = 32 stage: e0 region desc, e1 region asc
        #pragma unroll
        for (int j = 16; j > 0; j >>= 1) {
            k0 = ce(k0, j, true, lane);
            k1 = ce(k1, j, false, lane);
        }
        // k = 64 stage: j=32 is intra-thread, then j<=16 all desc
        {
            u64 lo = (k0 < k1) ? k0 : k1;
            u64 hi = (k0 < k1) ? k1 : k0;
            k0 = hi; k1 = lo;
        }
        #pragma unroll
        for (int j = 16; j > 0; j >>= 1) {
            k0 = ce(k0, j, true, lane);
            k1 = ce(k1, j, true, lane);
        }

        // Decode boxes (guard OOB loads for padding keys).
        float x10, y10, x20, y20, x11, y11, x21, y21;
        {
            u32 idx = ~(u32)k0;
            if (lane < cnt) {
                int a = idx / NC;
                const float* p = pred + ((size_t)img * NANCH + a) * NCH;
                float cx = __ldg(p), cy = __ldg(p + 1);
                float w  = __ldg(p + 2), h = __ldg(p + 3);
                x10 = cx - 0.5f * w; y10 = cy - 0.5f * h;
                x20 = cx + 0.5f * w; y20 = cy + 0.5f * h;
            } else { x10 = y10 = x20 = y20 = 0.f; }
        }
        {
            u32 idx = ~(u32)k1;
            if (lane + 32 < cnt) {
                int a = idx / NC;
                const float* p = pred + ((size_t)img * NANCH + a) * NCH;
                float cx = __ldg(p), cy = __ldg(p + 1);
                float w  = __ldg(p + 2), h = __ldg(p + 3);
                x11 = cx - 0.5f * w; y11 = cy - 0.5f * h;
                x21 = cx + 0.5f * w; y21 = cy + 0.5f * h;
            } else { x11 = y11 = x21 = y21 = 0.f; }
        }

        u64 alive = (cnt >= 64) ? ~0ull : ((1ull << cnt) - 1ull);
        for (int i = 0; i < cnt; i++) {
            if (!((alive >> i) & 1ull)) continue;
            bool hi = (i >= 32);
            int  sl = i & 31;
            float sx1 = hi ? x11 : x10, sy1 = hi ? y11 : y10;
            float sx2 = hi ? x21 : x20, sy2 = hi ? y21 : y20;
            float ax1 = __shfl_sync(FULL, sx1, sl);
            float ay1 = __shfl_sync(FULL, sy1, sl);
            float ax2 = __shfl_sync(FULL, sx2, sl);
            float ay2 = __shfl_sync(FULL, sy2, sl);
            float areaA = (ax2 - ax1) * (ay2 - ay1);

            float iw0 = fminf(ax2, x20) - fmaxf(ax1, x10);
            float ih0 = fminf(ay2, y20) - fmaxf(ay1, y10);
            float in0 = fmaxf(iw0, 0.f) * fmaxf(ih0, 0.f);
            float ar0 = (x20 - x10) * (y20 - y10);
            float iou0 = in0 / (areaA + ar0 - in0 + 1e-9f);

            float iw1 = fminf(ax2, x21) - fmaxf(ax1, x11);
            float ih1 = fminf(ay2, y21) - fmaxf(ay1, y11);
            float in1 = fmaxf(iw1, 0.f) * fmaxf(ih1, 0.f);
            float ar1 = (x21 - x11) * (y21 - y11);
            float iou1 = in1 / (areaA + ar1 - in1 + 1e-9f);

            u32 m0 = __ballot_sync(FULL, (lane > i) && (iou0 > IOUT));
            u32 m1 = __ballot_sync(FULL, ((lane + 32) > i) && (iou1 > IOUT));
            alive &= ~(((u64)m1 << 32) | (u64)m0);
        }

        // Append kept keys (order irrelevant; K3 re-orders deterministically).
        u32 klo = (u32)alive, khi = (u32)(alive >> 32);
        int tot = __popc(klo) + __popc(khi);
        int base = 0;
        if (lane == 0) base = atomicAdd(&g_kcount[img], tot);
        base = __shfl_sync(FULL, base, 0);
        if ((klo >> lane) & 1u) {
            int p = base + __popc(klo & ((1u << lane) - 1u));
            if (p < KEPTCAP) g_kept[img * KEPTCAP + p] = k0;
        }
        if ((khi >> lane) & 1u) {
            int p = base + __popc(klo) + __popc(khi & ((1u << lane) - 1u));
            if (p < KEPTCAP) g_kept[img * KEPTCAP + p] = k1;
        }
    }
    if (lane == 0) g_ccount[img * NC + c] = 0;  // clean for next replay
}

// ---------------------------------------------------------------------------
// K3: per image: exact top-300 (ordered) of kept keys via histogram select +
// bitonic-512 sort, then emit rows and reset counters.
// ---------------------------------------------------------------------------
__global__ __launch_bounds__(1024) void k_out(const float* __restrict__ pred,
                                              float* __restrict__ out) {
    __shared__ u32 hist[NBIN];
    __shared__ u32 ssa[NBIN];       // strictly-above counts per bin
    __shared__ u64 setk[512];
    __shared__ u32 wsums[32];
    __shared__ int scnt;

    int img  = blockIdx.x;
    int tid  = threadIdx.x;
    int lane = tid & 31;
    int warp = tid >> 5;

    int M = g_kcount[img];
    if (M > KEPTCAP) M = KEPTCAP;

    for (int i = tid; i < NBIN; i += 1024) hist[i] = 0;
    if (tid == 0) scnt = 0;
    __syncthreads();

    const u64* kp = &g_kept[img * KEPTCAP];
    for (int i = tid; i < M; i += 1024) {
        u32 h = ((u32)(kp[i] >> 32) - SB0) >> 8;
        atomicAdd(&hist[h], 1u);
    }
    __syncthreads();

    // Suffix-exclusive scan over 4096 bins (higher bin = higher score).
    int b0i = 4 * tid;
    u32 c0 = hist[b0i], c1 = hist[b0i + 1], c2 = hist[b0i + 2], c3 = hist[b0i + 3];
    u32 T = c0 + c1 + c2 + c3;
    u32 v = T;
    #pragma unroll
    for (int o = 1; o < 32; o <<= 1) {
        u32 u = __shfl_down_sync(FULL, v, o);
        if (lane + o < 32) v += u;
    }
    u32 exw = v - T;                 // sum over higher lanes in this warp
    if (lane == 0) wsums[warp] = v;  // inclusive warp suffix total
    __syncthreads();
    if (warp == 0) {
        u32 wv = wsums[lane];
        u32 s = wv;
        #pragma unroll
        for (int o = 1; o < 32; o <<= 1) {
            u32 u = __shfl_down_sync(FULL, s, o);
            if (lane + o < 32) s += u;
        }
        wsums[lane] = s - wv;        // sum over higher warps
    }
    __syncthreads();
    u32 above = wsums[warp] + exw;
    ssa[b0i + 3] = above;
    ssa[b0i + 2] = above + c3;
    ssa[b0i + 1] = above + c3 + c2;
    ssa[b0i + 0] = above + c3 + c2 + c1;
    __syncthreads();

    // Select: key is a top-300 contender iff < 300 kept in strictly higher bins.
    bool selAll = (M <= DETS);
    for (int i = tid; i < M; i += 1024) {
        u64 k = kp[i];
        u32 h = ((u32)(k >> 32) - SB0) >> 8;
        if (selAll || ssa[h] < DETS) {
            int p = atomicAdd(&scnt, 1);
            if (p < 512) setk[p] = k;
        }
    }
    __syncthreads();
    int S = scnt; if (S > 512) S = 512;
    if (tid < 512 && tid >= S) setk[tid] = 0ull;
    __syncthreads();

    // Bitonic sort 512 descending.
    for (int k = 2; k <= 512; k <<= 1) {
        for (int j = k >> 1; j > 0; j >>= 1) {
            if (tid < 256) {
                int i0 = ((tid & ~(j - 1)) << 1) | (tid & (j - 1));
                int i1 = i0 | j;
                u64 a = setk[i0], b = setk[i1];
                bool desc = ((i0 & k) == 0);
                if (desc ? (a < b) : (a > b)) { setk[i0] = b; setk[i1] = a; }
            }
            __syncthreads();
        }
    }

    // Emit rows.
    int K = (M < DETS) ? M : DETS;
    if (tid < DETS) {
        float r0 = 0.f, r1 = 0.f, r2 = 0.f, r3 = 0.f, r4 = 0.f, r5 = 0.f;
        if (tid < K) {
            u64 k = setk[tid];
            u32 idx = ~(u32)k;
            int a   = idx / NC;
            int cls = idx - a * NC;
            const float* p = pred + ((size_t)img * NANCH + a) * NCH;
            float cx = __ldg(p), cy = __ldg(p + 1);
            float w  = __ldg(p + 2), h = __ldg(p + 3);
            r0 = cx - 0.5f * w; r1 = cy - 0.5f * h;
            r2 = cx + 0.5f * w; r3 = cy + 0.5f * h;
            r4 = __uint_as_float((u32)(k >> 32));
            r5 = (float)cls;
        }
        float* o = out + ((size_t)img * DETS + tid) * 6;
        o[0] = r0; o[1] = r1; o[2] = r2; o[3] = r3; o[4] = r4; o[5] = r5;
    }
    __syncthreads();
    if (tid == 0) g_kcount[img] = 0;  // clean for next replay
}

extern "C" void kernel_launch(void* const* d_in, const int* in_sizes, int n_in,
                              void* d_out, int out_size) {
    const float* pred = (const float*)d_in[0];
    float* out = (float*)d_out;

    dim3 g1((NANCH + 255) / 256, NIMG);
    k_filter<<<g1, 256>>>(pred);
    k_nms<<<dim3(NIMG, 10), 256>>>(pred);
    k_out<<<NIMG, 1024>>>(pred, out);
}